// round 3
// baseline (speedup 1.0000x reference)
#include <cuda_runtime.h>
#include <cstdint>

#define D        256
#define KCODES   8192
#define NTOK     32768
#define BM       128
#define BK       64
#define TPB      256
#define NCHUNK   (KCODES / BK)          // 128
#define KSPLIT   4
#define CPS      (NCHUNK / KSPLIT)      // 32 chunks per split
#define GBLOCKS  (NTOK / 8)             // 4096 gather blocks
#define ZQ_ELEMS ((size_t)NTOK * D)     // 8388608
#define OUT_FULL (ZQ_ELEMS + 3 + NTOK)  // 8421379

typedef unsigned long long u64;

// ---- scratch (__device__ globals: the sanctioned no-alloc path) ----
__device__ float g_esq[KCODES];
__device__ float g_zsq[NTOK];
__device__ float g_cval[NTOK * KSPLIT];
__device__ int   g_cidx[NTOK * KSPLIT];
__device__ int   g_bidx[NTOK];
__device__ float g_part[GBLOCKS];

// ---- packed fp32x2 helpers (SASS FFMA2; per-lane IEEE fp32 fma) ----
__device__ __forceinline__ u64 pack2(float lo, float hi) {
    u64 r; asm("mov.b64 %0, {%1, %2};" : "=l"(r) : "f"(lo), "f"(hi)); return r;
}
__device__ __forceinline__ void fma2(u64& acc, u64 a, u64 b) {
    asm("fma.rn.f32x2 %0, %1, %2, %0;" : "+l"(acc) : "l"(a), "l"(b));
}
__device__ __forceinline__ void unpack2(u64 v, float& lo, float& hi) {
    asm("mov.b64 {%0, %1}, %2;" : "=f"(lo), "=f"(hi) : "l"(v));
}

// ============================================================
// Kernel 0a: per-code ||e_k||^2  — sequential fma chain (d-order)
// ============================================================
__global__ void esq_kernel(const float* __restrict__ emb) {
    int k = blockIdx.x * blockDim.x + threadIdx.x;
    if (k >= KCODES) return;
    const float4* row = reinterpret_cast<const float4*>(emb + (size_t)k * D);
    float s = 0.f;
#pragma unroll
    for (int i = 0; i < D / 4; ++i) {
        float4 v = row[i];
        s = fmaf(v.x, v.x, s); s = fmaf(v.y, v.y, s);
        s = fmaf(v.z, v.z, s); s = fmaf(v.w, v.w, s);
    }
    g_esq[k] = s;
}

// ============================================================
// Kernel 0b: per-token ||z_n||^2 — same sequential fma chain
// ============================================================
__global__ void zsq_kernel(const float* __restrict__ z) {
    int n = blockIdx.x * blockDim.x + threadIdx.x;
    if (n >= NTOK) return;
    const float4* row = reinterpret_cast<const float4*>(z + (size_t)n * D);
    float s = 0.f;
#pragma unroll 8
    for (int i = 0; i < D / 4; ++i) {
        float4 v = row[i];
        s = fmaf(v.x, v.x, s); s = fmaf(v.y, v.y, s);
        s = fmaf(v.z, v.z, s); s = fmaf(v.w, v.w, s);
    }
    g_zsq[n] = s;
}

// ============================================================
// Kernel 1: fused GEMM + quantized-score argmin, FFMA2 packed,
//           4-way K-split for wave balance.
//   grid = (NTOK/BM) * KSPLIT ; block bid -> tile = bid>>2, ks = bid&3
//   thread(ty,tx): tokens ty*8..+7 (4 packed pairs), codes {tx+16j}
//   dot chain: strictly sequential in d per (token, code) lane
//   score = fl( fl(zsq + esq) - 2*dot )  — reference-exact rounding
// ============================================================
__global__ __launch_bounds__(TPB, 1)
void argmin_kernel(const float* __restrict__ z, const float* __restrict__ emb) {
    extern __shared__ float smem[];
    float4* zs4 = reinterpret_cast<float4*>(smem);                  // [BM][64] f4
    float4* es4 = reinterpret_cast<float4*>(smem) + (BM * D / 4);   // [BK][65] f4 (pad)

    const int tid  = threadIdx.x;
    const int tx   = tid & 15;
    const int ty   = tid >> 4;
    const int tile = blockIdx.x >> 2;
    const int ks   = blockIdx.x & 3;

    // stage the 128-token z tile
    const float4* zg4 = reinterpret_cast<const float4*>(z + (size_t)tile * BM * D);
#pragma unroll 4
    for (int i = tid; i < BM * D / 4; i += TPB) zs4[i] = zg4[i];

    float zq[8];
#pragma unroll
    for (int i = 0; i < 8; ++i) zq[i] = g_zsq[tile * BM + ty * 8 + i];

    float best[8];
    int   bidx[8];
#pragma unroll
    for (int i = 0; i < 8; ++i) { best[i] = 3.4e38f; bidx[i] = 0; }

    for (int kc = ks * CPS; kc < ks * CPS + CPS; ++kc) {
        __syncthreads();
        const float4* eg4 = reinterpret_cast<const float4*>(emb + (size_t)kc * BK * D);
#pragma unroll 4
        for (int i = tid; i < BK * D / 4; i += TPB) {
            int row = i >> 6, c = i & 63;
            es4[row * 65 + c] = eg4[i];
        }
        __syncthreads();

        u64 acc[4][4];   // [token-pair][code] ; lane0 = token 2p, lane1 = token 2p+1
#pragma unroll
        for (int p = 0; p < 4; ++p)
#pragma unroll
            for (int j = 0; j < 4; ++j) acc[p][j] = 0ull;

#pragma unroll 4
        for (int d4 = 0; d4 < D / 4; ++d4) {
            float4 zf[8];
#pragma unroll
            for (int i = 0; i < 8; ++i) zf[i] = zs4[(ty * 8 + i) * (D / 4) + d4];
            float4 ef[4];
#pragma unroll
            for (int j = 0; j < 4; ++j) ef[j] = es4[(tx + 16 * j) * 65 + d4];

#pragma unroll
            for (int dd = 0; dd < 4; ++dd) {
                u64 az[4], be[4];
#pragma unroll
                for (int p = 0; p < 4; ++p) {
                    float zlo = ((const float*)&zf[2 * p])[dd];
                    float zhi = ((const float*)&zf[2 * p + 1])[dd];
                    az[p] = pack2(zlo, zhi);
                }
#pragma unroll
                for (int j = 0; j < 4; ++j) {
                    float ev = ((const float*)&ef[j])[dd];
                    be[j] = pack2(ev, ev);
                }
#pragma unroll
                for (int p = 0; p < 4; ++p)
#pragma unroll
                    for (int j = 0; j < 4; ++j)
                        fma2(acc[p][j], az[p], be[j]);
            }
        }

        // reference-exact score + running first-min
#pragma unroll
        for (int j = 0; j < 4; ++j) {
            int code = kc * BK + tx + 16 * j;
            float e2 = g_esq[code];
#pragma unroll
            for (int p = 0; p < 4; ++p) {
                float dlo, dhi;
                unpack2(acc[p][j], dlo, dhi);
                float t1 = __fadd_rn(zq[2 * p], e2);
                float s  = __fadd_rn(t1, -2.0f * dlo);
                if (s < best[2 * p]) { best[2 * p] = s; bidx[2 * p] = code; }
                float t2 = __fadd_rn(zq[2 * p + 1], e2);
                float s2 = __fadd_rn(t2, -2.0f * dhi);
                if (s2 < best[2 * p + 1]) { best[2 * p + 1] = s2; bidx[2 * p + 1] = code; }
            }
        }
    }

    // reduce across the 16 tx-threads per token (lexicographic min, first-index ties)
#pragma unroll
    for (int m = 8; m >= 1; m >>= 1) {
#pragma unroll
        for (int i = 0; i < 8; ++i) {
            float ov = __shfl_xor_sync(0xffffffffu, best[i], m);
            int   oi = __shfl_xor_sync(0xffffffffu, bidx[i], m);
            if (ov < best[i] || (ov == best[i] && oi < bidx[i])) { best[i] = ov; bidx[i] = oi; }
        }
    }
    if (tx == 0) {
#pragma unroll
        for (int i = 0; i < 8; ++i) {
            int n = tile * BM + ty * 8 + i;
            g_cval[n * KSPLIT + ks] = best[i];
            g_cidx[n * KSPLIT + ks] = bidx[i];
        }
    }
}

// ============================================================
// Kernel 1b: merge K-split candidates (splits ascend in code range,
// so equal-value ties resolve to the lower split = lower index)
// ============================================================
__global__ void merge_kernel() {
    int n = blockIdx.x * blockDim.x + threadIdx.x;
    if (n >= NTOK) return;
    float bv = g_cval[n * KSPLIT];
    int   bi = g_cidx[n * KSPLIT];
#pragma unroll
    for (int s = 1; s < KSPLIT; ++s) {
        float v = g_cval[n * KSPLIT + s];
        int   i = g_cidx[n * KSPLIT + s];
        if (v < bv || (v == bv && i < bi)) { bv = v; bi = i; }
    }
    g_bidx[n] = bi;
}

// ============================================================
// Kernel 2: gather + straight-through output + loss partials
//   exact replication of fl(z + fl(e - z))
// ============================================================
__global__ void gather_kernel(const float* __restrict__ z, const float* __restrict__ emb,
                              float* __restrict__ out, int out_size) {
    __shared__ float wsum[8];
    const int lane = threadIdx.x & 31;
    const int wib  = threadIdx.x >> 5;
    const int n    = blockIdx.x * 8 + wib;

    const int idx = g_bidx[n];
    const float4* zr = reinterpret_cast<const float4*>(z   + (size_t)n   * D);
    const float4* er = reinterpret_cast<const float4*>(emb + (size_t)idx * D);
    float4* orow = reinterpret_cast<float4*>(out + (size_t)n * D);

    float ss = 0.f;
#pragma unroll
    for (int i = lane; i < D / 4; i += 32) {
        float4 zv = zr[i], ev = er[i], df, ov;
        df.x = ev.x - zv.x; df.y = ev.y - zv.y; df.z = ev.z - zv.z; df.w = ev.w - zv.w;
        ov.x = zv.x + df.x; ov.y = zv.y + df.y; ov.z = zv.z + df.z; ov.w = zv.w + df.w;
        ss = fmaf(df.x, df.x, ss); ss = fmaf(df.y, df.y, ss);
        ss = fmaf(df.z, df.z, ss); ss = fmaf(df.w, df.w, ss);
        if ((size_t)out_size >= ZQ_ELEMS) orow[i] = ov;
    }
#pragma unroll
    for (int m = 16; m >= 1; m >>= 1) ss += __shfl_xor_sync(0xffffffffu, ss, m);
    if (lane == 0) wsum[wib] = ss;
    __syncthreads();
    if (threadIdx.x == 0) {
        float t = 0.f;
#pragma unroll
        for (int w = 0; w < 8; ++w) t += wsum[w];
        g_part[blockIdx.x] = t;
    }
    if (lane == 0 && (size_t)out_size >= OUT_FULL)
        out[ZQ_ELEMS + 3 + n] = (float)idx;
}

// ============================================================
// Kernel 3: deterministic loss finalize (double accumulation)
// ============================================================
__global__ void loss_kernel(float* __restrict__ out, int out_size) {
    __shared__ double sh[256];
    const int t = threadIdx.x;
    double s = 0.0;
#pragma unroll 4
    for (int i = t * (GBLOCKS / 256); i < (t + 1) * (GBLOCKS / 256); ++i)
        s += (double)g_part[i];
    sh[t] = s;
    __syncthreads();
    for (int m = 128; m >= 1; m >>= 1) {
        if (t < m) sh[t] += sh[t + m];
        __syncthreads();
    }
    if (t == 0 && (size_t)out_size >= ZQ_ELEMS + 3) {
        float mean = (float)(sh[0] / (double)ZQ_ELEMS);
        float commit   = 0.25f * mean;
        float codebook = mean;
        out[ZQ_ELEMS + 0] = commit + codebook;
        out[ZQ_ELEMS + 1] = commit;
        out[ZQ_ELEMS + 2] = codebook;
    }
}

// ============================================================
extern "C" void kernel_launch(void* const* d_in, const int* in_sizes, int n_in,
                              void* d_out, int out_size) {
    const float* z   = (const float*)d_in[0];
    const float* emb = (const float*)d_in[1];
    if (n_in >= 2 && in_sizes[0] == KCODES * D && in_sizes[1] == NTOK * D) {
        z   = (const float*)d_in[1];
        emb = (const float*)d_in[0];
    }
    float* out = (float*)d_out;

    static bool attr_set = false;
    const int smem_bytes = (BM * D + BK * 260) * (int)sizeof(float);   // 197632
    if (!attr_set) {
        cudaFuncSetAttribute(argmin_kernel,
                             cudaFuncAttributeMaxDynamicSharedMemorySize, smem_bytes);
        attr_set = true;
    }

    esq_kernel<<<KCODES / 128, 128>>>(emb);
    zsq_kernel<<<NTOK / 256, 256>>>(z);
    argmin_kernel<<<(NTOK / BM) * KSPLIT, TPB, smem_bytes>>>(z, emb);
    merge_kernel<<<NTOK / 256, 256>>>();
    gather_kernel<<<GBLOCKS, 256>>>(z, emb, out, out_size);
    loss_kernel<<<1, 256>>>(out, out_size);
}

// round 4
// speedup vs baseline: 1.0275x; 1.0275x over previous
#include <cuda_runtime.h>
#include <cstdint>

#define D        256
#define KCODES   8192
#define NTOK     32768
#define BM       128
#define BK       32
#define TPB      256
#define NCHUNK   (KCODES / BK)          // 256
#define KSPLIT   4
#define CPS      (NCHUNK / KSPLIT)      // 64 chunks per split
#define GBLOCKS  (NTOK / 8)             // 4096 gather blocks
#define ZQ_ELEMS ((size_t)NTOK * D)     // 8388608
#define OUT_FULL (ZQ_ELEMS + 3 + NTOK)  // 8421379

#define PITCH2   258                    // float2 pitch per row (2064B): 16B-aligned, bank-clean

typedef unsigned long long u64;

// ---- scratch (__device__ globals: sanctioned no-alloc path) ----
__device__ float g_esq[KCODES];
__device__ float g_zsq[NTOK];
__device__ float g_cval[NTOK * KSPLIT];
__device__ int   g_cidx[NTOK * KSPLIT];
__device__ int   g_bidx[NTOK];
__device__ float g_part[GBLOCKS];

// ---- packed fp32x2 helpers (per-lane IEEE fp32 fma) ----
__device__ __forceinline__ void fma2(u64& acc, u64 a, u64 b) {
    asm("fma.rn.f32x2 %0, %1, %2, %0;" : "+l"(acc) : "l"(a), "l"(b));
}
__device__ __forceinline__ void unpack2(u64 v, float& lo, float& hi) {
    asm("mov.b64 {%0, %1}, %2;" : "=f"(lo), "=f"(hi) : "l"(v));
}

// ============================================================
// Kernel 0a: per-code ||e_k||^2  — sequential fma chain (d-order)
// ============================================================
__global__ void esq_kernel(const float* __restrict__ emb) {
    int k = blockIdx.x * blockDim.x + threadIdx.x;
    if (k >= KCODES) return;
    const float4* row = reinterpret_cast<const float4*>(emb + (size_t)k * D);
    float s = 0.f;
#pragma unroll
    for (int i = 0; i < D / 4; ++i) {
        float4 v = row[i];
        s = fmaf(v.x, v.x, s); s = fmaf(v.y, v.y, s);
        s = fmaf(v.z, v.z, s); s = fmaf(v.w, v.w, s);
    }
    g_esq[k] = s;
}

// ============================================================
// Kernel 0b: per-token ||z_n||^2 — same sequential fma chain
// ============================================================
__global__ void zsq_kernel(const float* __restrict__ z) {
    int n = blockIdx.x * blockDim.x + threadIdx.x;
    if (n >= NTOK) return;
    const float4* row = reinterpret_cast<const float4*>(z + (size_t)n * D);
    float s = 0.f;
#pragma unroll 8
    for (int i = 0; i < D / 4; ++i) {
        float4 v = row[i];
        s = fmaf(v.x, v.x, s); s = fmaf(v.y, v.y, s);
        s = fmaf(v.z, v.z, s); s = fmaf(v.w, v.w, s);
    }
    g_zsq[n] = s;
}

// ============================================================
// Kernel 1: fused GEMM + quantized-score argmin.
//   FFMA2 with memory-packed operands:
//     zp[pair][d] = (z[2p][d], z[2p+1][d])   — LDS.128 -> 2 packed ops
//     de[code][d] = (e[c][d], e[c][d])       — LDS.128 -> 2 packed ops
//   Per-acc d-chain strictly sequential  -> bit-exact vs reference.
//   score = fl( fl(zsq+esq) - 2*dot ), first-index argmin.
//   grid = (NTOK/BM)*KSPLIT; e chunks register-prefetched.
// ============================================================
__global__ __launch_bounds__(TPB, 1)
void argmin_kernel(const float* __restrict__ z, const float* __restrict__ emb) {
    extern __shared__ float2 sm2[];
    float2* zp = sm2;                       // [64 pairs][PITCH2]
    float2* de = sm2 + 64 * PITCH2;         // [32 codes][PITCH2]

    const int tid  = threadIdx.x;
    const int tx   = tid & 15;              // codes tx, tx+16
    const int ty   = tid >> 4;              // token pairs ty*4 .. ty*4+3
    const int tile = blockIdx.x >> 2;
    const int ks   = blockIdx.x & 3;

    // ---- stage z tile, token-pair interleaved ----
    const float4* zg4 = reinterpret_cast<const float4*>(z + (size_t)tile * BM * D);
#pragma unroll 4
    for (int i = tid; i < 64 * 64; i += TPB) {       // pair p = i>>6, d4 = i&63
        int p = i >> 6, d4 = i & 63;
        float4 a = zg4[(2 * p) * 64 + d4];
        float4 b = zg4[(2 * p + 1) * 64 + d4];
        float2* dst = &zp[p * PITCH2 + d4 * 4];
        *reinterpret_cast<float4*>(dst)     = make_float4(a.x, b.x, a.y, b.y);
        *reinterpret_cast<float4*>(dst + 2) = make_float4(a.z, b.z, a.w, b.w);
    }

    float zq[8];
#pragma unroll
    for (int i = 0; i < 8; ++i) zq[i] = g_zsq[tile * BM + ty * 8 + i];

    float best[8];
    int   bidx[8];
#pragma unroll
    for (int i = 0; i < 8; ++i) { best[i] = 3.4e38f; bidx[i] = 0; }

    const int c0 = ks * CPS, c1 = c0 + CPS;

    // prefetch first e chunk into registers (BK*D = 2048 float4 / 256 thr = 8)
    float4 pf[8];
    {
        const float4* eg = reinterpret_cast<const float4*>(emb + (size_t)c0 * BK * D);
#pragma unroll
        for (int k = 0; k < 8; ++k) pf[k] = eg[tid + 256 * k];
    }

    const float2* zpr = zp + (ty * 4) * PITCH2;
    const float2* der = de + tx * PITCH2;

    for (int kc = c0; kc < c1; ++kc) {
        __syncthreads();   // previous chunk's readers done (also orders zp staging)

        // write duplicated e chunk from prefetch regs
#pragma unroll
        for (int k = 0; k < 8; ++k) {
            int u = tid + 256 * k;
            float4 v = pf[k];
            float2* dst = &de[(u >> 6) * PITCH2 + (u & 63) * 4];
            *reinterpret_cast<float4*>(dst)     = make_float4(v.x, v.x, v.y, v.y);
            *reinterpret_cast<float4*>(dst + 2) = make_float4(v.z, v.z, v.w, v.w);
        }
        // prefetch next chunk (hidden under this chunk's compute)
        if (kc + 1 < c1) {
            const float4* eg = reinterpret_cast<const float4*>(emb + (size_t)(kc + 1) * BK * D);
#pragma unroll
            for (int k = 0; k < 8; ++k) pf[k] = eg[tid + 256 * k];
        }
        float e2a = g_esq[kc * BK + tx];
        float e2b = g_esq[kc * BK + tx + 16];
        __syncthreads();

        u64 acc[4][2];
#pragma unroll
        for (int p = 0; p < 4; ++p) { acc[p][0] = 0ull; acc[p][1] = 0ull; }

#pragma unroll 4
        for (int d4 = 0; d4 < 64; ++d4) {
#pragma unroll
            for (int h = 0; h < 2; ++h) {
                const int d = d4 * 4 + h * 2;
                ulonglong2 B0 = *reinterpret_cast<const ulonglong2*>(der + d);
                ulonglong2 B1 = *reinterpret_cast<const ulonglong2*>(der + 16 * PITCH2 + d);
#pragma unroll
                for (int p = 0; p < 4; ++p) {
                    ulonglong2 A = *reinterpret_cast<const ulonglong2*>(zpr + p * PITCH2 + d);
                    fma2(acc[p][0], A.x, B0.x);
                    fma2(acc[p][1], A.x, B1.x);
                    fma2(acc[p][0], A.y, B0.y);   // d then d+1: sequential chain
                    fma2(acc[p][1], A.y, B1.y);
                }
            }
        }

        // reference-exact score + running first-min (j=0 codes before j=1)
#pragma unroll
        for (int j = 0; j < 2; ++j) {
            int   code = kc * BK + tx + 16 * j;
            float e2   = (j == 0) ? e2a : e2b;
#pragma unroll
            for (int p = 0; p < 4; ++p) {
                float dlo, dhi;
                unpack2(acc[p][j], dlo, dhi);
                float t1 = __fadd_rn(zq[2 * p], e2);
                float s  = __fadd_rn(t1, -2.0f * dlo);
                if (s < best[2 * p]) { best[2 * p] = s; bidx[2 * p] = code; }
                float t2 = __fadd_rn(zq[2 * p + 1], e2);
                float s2 = __fadd_rn(t2, -2.0f * dhi);
                if (s2 < best[2 * p + 1]) { best[2 * p + 1] = s2; bidx[2 * p + 1] = code; }
            }
        }
    }

    // reduce across the 16 tx-threads per token (lexicographic, first-index ties)
#pragma unroll
    for (int m = 8; m >= 1; m >>= 1) {
#pragma unroll
        for (int i = 0; i < 8; ++i) {
            float ov = __shfl_xor_sync(0xffffffffu, best[i], m);
            int   oi = __shfl_xor_sync(0xffffffffu, bidx[i], m);
            if (ov < best[i] || (ov == best[i] && oi < bidx[i])) { best[i] = ov; bidx[i] = oi; }
        }
    }
    if (tx == 0) {
#pragma unroll
        for (int i = 0; i < 8; ++i) {
            int n = tile * BM + ty * 8 + i;
            g_cval[n * KSPLIT + ks] = best[i];
            g_cidx[n * KSPLIT + ks] = bidx[i];
        }
    }
}

// ============================================================
// Kernel 1b: merge K-split candidates (splits ascend in code range)
// ============================================================
__global__ void merge_kernel() {
    int n = blockIdx.x * blockDim.x + threadIdx.x;
    if (n >= NTOK) return;
    float bv = g_cval[n * KSPLIT];
    int   bi = g_cidx[n * KSPLIT];
#pragma unroll
    for (int s = 1; s < KSPLIT; ++s) {
        float v = g_cval[n * KSPLIT + s];
        int   i = g_cidx[n * KSPLIT + s];
        if (v < bv || (v == bv && i < bi)) { bv = v; bi = i; }
    }
    g_bidx[n] = bi;
}

// ============================================================
// Kernel 2: gather + straight-through output + loss partials
//   exact replication of fl(z + fl(e - z))
// ============================================================
__global__ void gather_kernel(const float* __restrict__ z, const float* __restrict__ emb,
                              float* __restrict__ out, int out_size) {
    __shared__ float wsum[8];
    const int lane = threadIdx.x & 31;
    const int wib  = threadIdx.x >> 5;
    const int n    = blockIdx.x * 8 + wib;

    const int idx = g_bidx[n];
    const float4* zr = reinterpret_cast<const float4*>(z   + (size_t)n   * D);
    const float4* er = reinterpret_cast<const float4*>(emb + (size_t)idx * D);
    float4* orow = reinterpret_cast<float4*>(out + (size_t)n * D);

    float ss = 0.f;
#pragma unroll
    for (int i = lane; i < D / 4; i += 32) {
        float4 zv = zr[i], ev = er[i], df, ov;
        df.x = ev.x - zv.x; df.y = ev.y - zv.y; df.z = ev.z - zv.z; df.w = ev.w - zv.w;
        ov.x = zv.x + df.x; ov.y = zv.y + df.y; ov.z = zv.z + df.z; ov.w = zv.w + df.w;
        ss = fmaf(df.x, df.x, ss); ss = fmaf(df.y, df.y, ss);
        ss = fmaf(df.z, df.z, ss); ss = fmaf(df.w, df.w, ss);
        if ((size_t)out_size >= ZQ_ELEMS) orow[i] = ov;
    }
#pragma unroll
    for (int m = 16; m >= 1; m >>= 1) ss += __shfl_xor_sync(0xffffffffu, ss, m);
    if (lane == 0) wsum[wib] = ss;
    __syncthreads();
    if (threadIdx.x == 0) {
        float t = 0.f;
#pragma unroll
        for (int w = 0; w < 8; ++w) t += wsum[w];
        g_part[blockIdx.x] = t;
    }
    if (lane == 0 && (size_t)out_size >= OUT_FULL)
        out[ZQ_ELEMS + 3 + n] = (float)idx;
}

// ============================================================
// Kernel 3: deterministic loss finalize (double accumulation)
// ============================================================
__global__ void loss_kernel(float* __restrict__ out, int out_size) {
    __shared__ double sh[256];
    const int t = threadIdx.x;
    double s = 0.0;
#pragma unroll 4
    for (int i = t * (GBLOCKS / 256); i < (t + 1) * (GBLOCKS / 256); ++i)
        s += (double)g_part[i];
    sh[t] = s;
    __syncthreads();
    for (int m = 128; m >= 1; m >>= 1) {
        if (t < m) sh[t] += sh[t + m];
        __syncthreads();
    }
    if (t == 0 && (size_t)out_size >= ZQ_ELEMS + 3) {
        float mean = (float)(sh[0] / (double)ZQ_ELEMS);
        float commit   = 0.25f * mean;
        float codebook = mean;
        out[ZQ_ELEMS + 0] = commit + codebook;
        out[ZQ_ELEMS + 1] = commit;
        out[ZQ_ELEMS + 2] = codebook;
    }
}

// ============================================================
extern "C" void kernel_launch(void* const* d_in, const int* in_sizes, int n_in,
                              void* d_out, int out_size) {
    const float* z   = (const float*)d_in[0];
    const float* emb = (const float*)d_in[1];
    if (n_in >= 2 && in_sizes[0] == KCODES * D && in_sizes[1] == NTOK * D) {
        z   = (const float*)d_in[1];
        emb = (const float*)d_in[0];
    }
    float* out = (float*)d_out;

    static bool attr_set = false;
    const int smem_bytes = (64 + 32) * PITCH2 * (int)sizeof(float2);   // 198144
    if (!attr_set) {
        cudaFuncSetAttribute(argmin_kernel,
                             cudaFuncAttributeMaxDynamicSharedMemorySize, smem_bytes);
        attr_set = true;
    }

    esq_kernel<<<KCODES / 128, 128>>>(emb);
    zsq_kernel<<<NTOK / 256, 256>>>(z);
    argmin_kernel<<<(NTOK / BM) * KSPLIT, TPB, smem_bytes>>>(z, emb);
    merge_kernel<<<NTOK / 256, 256>>>();
    gather_kernel<<<GBLOCKS, 256>>>(z, emb, out, out_size);
    loss_kernel<<<1, 256>>>(out, out_size);
}

// round 6
// speedup vs baseline: 3.4944x; 3.4008x over previous
#include <cuda_runtime.h>
#include <cuda_bf16.h>
#include <cstdint>

#define D        256
#define KCODES   8192
#define NTOK     32768
#define CTAM     128
#define CTAN     128
#define NTILES   (NTOK / CTAM)       // 256
#define NCHUNKS  (KCODES / CTAN)     // 64
#define NSPLIT   4
#define CPS      (NCHUNKS / NSPLIT)  // 16
#define CAP      64
#define WINDOW   5.0e-4f
#define GBLOCKS  (NTOK / 8)
#define ZQ_ELEMS ((size_t)NTOK * D)
#define OUT_FULL (ZQ_ELEMS + 3 + NTOK)

// smem layout (bytes): padded bf16 rows, 264 elems = 528B (4-bank rotation)
#define SROW     528
#define ZS_BYTES (CTAM * SROW)                   // 67584
#define ES_OFF(b)  (ZS_BYTES + (b) * ZS_BYTES)   // two e buffers
#define ESQ_OFF(b) (3 * ZS_BYTES + (b) * 512)
#define SMEM_TOTAL (3 * ZS_BYTES + 1024)         // 203776

// ---- scratch (__device__ globals: sanctioned no-alloc path) ----
__device__ float          g_esq[KCODES];
__device__ float          g_zsq[NTOK];
__device__ unsigned short g_zbf[(size_t)NTOK * D];    // bf16 row-major
__device__ unsigned short g_ebf[(size_t)KCODES * D];  // bf16 row-major
__device__ int            g_ccount[NTOK];
__device__ int            g_cand[(size_t)NTOK * CAP];
__device__ int            g_bidx[NTOK];
__device__ float          g_part[GBLOCKS];

// ============================================================
// PTX helpers (baseline ISA only: sm_80-level, no 'a' features)
// ============================================================
__device__ __forceinline__ uint32_t smem_u32(const void* p) {
    uint32_t a;
    asm("{ .reg .u64 t; cvta.to.shared.u64 t, %1; cvt.u32.u64 %0, t; }" : "=r"(a) : "l"(p));
    return a;
}
__device__ __forceinline__ void cpa16(uint32_t dst, const void* src) {
    asm volatile("cp.async.cg.shared.global [%0], [%1], 16;" :: "r"(dst), "l"(src));
}
#define CP_COMMIT() asm volatile("cp.async.commit_group;" ::: "memory")
#define CP_WAIT0()  asm volatile("cp.async.wait_group 0;" ::: "memory")

__device__ __forceinline__ void ldsm4(uint32_t& r0, uint32_t& r1, uint32_t& r2, uint32_t& r3,
                                      uint32_t addr) {
    asm volatile("ldmatrix.sync.aligned.m8n8.x4.shared.b16 {%0,%1,%2,%3}, [%4];"
                 : "=r"(r0), "=r"(r1), "=r"(r2), "=r"(r3) : "r"(addr));
}
__device__ __forceinline__ void mma_bf16(float& c0, float& c1, float& c2, float& c3,
                                         uint32_t a0, uint32_t a1, uint32_t a2, uint32_t a3,
                                         uint32_t b0, uint32_t b1) {
    asm volatile("mma.sync.aligned.m16n8k16.row.col.f32.bf16.bf16.f32 "
                 "{%0,%1,%2,%3}, {%4,%5,%6,%7}, {%8,%9}, {%0,%1,%2,%3};"
                 : "+f"(c0), "+f"(c1), "+f"(c2), "+f"(c3)
                 : "r"(a0), "r"(a1), "r"(a2), "r"(a3), "r"(b0), "r"(b1));
}
__device__ __forceinline__ uint32_t pack_bf(float lo, float hi) {
    __nv_bfloat162 v = __floats2bfloat162_rn(lo, hi);
    return *reinterpret_cast<uint32_t*>(&v);
}

// ============================================================
// Kernel 0a/0b: exact sequential ||e||^2 / ||z||^2 chains (bit-critical)
// ============================================================
__global__ void esq_kernel(const float* __restrict__ emb) {
    int k = blockIdx.x * blockDim.x + threadIdx.x;
    if (k >= KCODES) return;
    const float4* row = reinterpret_cast<const float4*>(emb + (size_t)k * D);
    float s = 0.f;
#pragma unroll
    for (int i = 0; i < D / 4; ++i) {
        float4 v = row[i];
        s = fmaf(v.x, v.x, s); s = fmaf(v.y, v.y, s);
        s = fmaf(v.z, v.z, s); s = fmaf(v.w, v.w, s);
    }
    g_esq[k] = s;
}
__global__ void zsq_kernel(const float* __restrict__ z) {
    int n = blockIdx.x * blockDim.x + threadIdx.x;
    if (n >= NTOK) return;
    const float4* row = reinterpret_cast<const float4*>(z + (size_t)n * D);
    float s = 0.f;
#pragma unroll 8
    for (int i = 0; i < D / 4; ++i) {
        float4 v = row[i];
        s = fmaf(v.x, v.x, s); s = fmaf(v.y, v.y, s);
        s = fmaf(v.z, v.z, s); s = fmaf(v.w, v.w, s);
    }
    g_zsq[n] = s;
}

// ============================================================
// Kernel 0c/0d: fp32 -> bf16 row-major copies (one thread / 8 elems)
// ============================================================
__global__ void convz_kernel(const float* __restrict__ z) {
    int t = blockIdx.x * blockDim.x + threadIdx.x;      // NTOK*32 threads
    int n = t >> 5, c8 = (t & 31) * 8;
    const float4* src = reinterpret_cast<const float4*>(z + (size_t)n * D + c8);
    float4 a = src[0], b = src[1];
    uint4 w = make_uint4(pack_bf(a.x, a.y), pack_bf(a.z, a.w),
                         pack_bf(b.x, b.y), pack_bf(b.z, b.w));
    *reinterpret_cast<uint4*>(g_zbf + (size_t)n * D + c8) = w;
}
__global__ void conve_kernel(const float* __restrict__ emb) {
    int t = blockIdx.x * blockDim.x + threadIdx.x;      // KCODES*32 threads
    int k = t >> 5, c8 = (t & 31) * 8;
    const float4* src = reinterpret_cast<const float4*>(emb + (size_t)k * D + c8);
    float4 a = src[0], b = src[1];
    uint4 w = make_uint4(pack_bf(a.x, a.y), pack_bf(a.z, a.w),
                         pack_bf(b.x, b.y), pack_bf(b.z, b.w));
    *reinterpret_cast<uint4*>(g_ebf + (size_t)k * D + c8) = w;
}

__global__ void init_kernel() {
    int n = blockIdx.x * blockDim.x + threadIdx.x;
    if (n < NTOK) g_ccount[n] = 0;
}

// ============================================================
// Kernel 1: bf16 mma.sync GEMM + running-min candidate filter.
//   grid = NTILES*NSPLIT, 256 threads (8 warps).
//   Warp w owns tokens tile*128 + w*16 .. +15, all 128 codes of chunk.
//   Per chunk: 16 k-steps, A via 1 ldmatrix.x4, B via 8 ldmatrix.x4,
//   16 mma; epilogue computes approx scores, updates per-token running
//   min (incl. current chunk), collects codes with s <= runmin + W.
// ============================================================
__global__ __launch_bounds__(256, 1)
void filter_kernel() {
    extern __shared__ char smc[];
    const uint32_t sb = smem_u32(smc);
    const int tid = threadIdx.x, wid = tid >> 5, lane = tid & 31;
    const int tile = blockIdx.x >> 2;
    const int sp   = blockIdx.x & 3;
    const int g = lane >> 2, t4 = lane & 3;

    // ---- stage z tile + chunk 0 (+esq) via cp.async ----
    {
        const char* zsrc = (const char*)(g_zbf + (size_t)tile * CTAM * D);
#pragma unroll 4
        for (int i = tid; i < 4096; i += 256) {
            int r = i >> 5, c = i & 31;
            cpa16(sb + r * SROW + c * 16, zsrc + r * 512 + c * 16);
        }
        int chunk0 = sp * CPS;
        const char* esrc = (const char*)(g_ebf + (size_t)chunk0 * CTAN * D);
#pragma unroll 4
        for (int i = tid; i < 4096; i += 256) {
            int r = i >> 5, c = i & 31;
            cpa16(sb + ES_OFF(0) + r * SROW + c * 16, esrc + r * 512 + c * 16);
        }
        if (tid < 32) cpa16(sb + ESQ_OFF(0) + tid * 16,
                            (const char*)(g_esq + chunk0 * CTAN) + tid * 16);
        CP_COMMIT();
    }

    // per-lane fragment address bases
    const uint32_t aBase = sb + (uint32_t)(wid * 16 + (lane & 15)) * SROW
                              + (uint32_t)((lane >> 4) * 8) * 2;
    const uint32_t bRowOff = (uint32_t)((lane & 7) + ((lane & 16) ? 8 : 0)) * SROW
                           + (uint32_t)((lane & 8) ? 8 : 0) * 2;

    const int tokg  = tile * CTAM + wid * 16 + g;
    const float zq0 = g_zsq[tokg];
    const float zq1 = g_zsq[tokg + 8];
    float run0 = 3.4e38f, run1 = 3.4e38f;

    for (int cl = 0; cl < CPS; ++cl) {
        const int cur = cl & 1;
        CP_WAIT0();
        __syncthreads();
        if (cl + 1 < CPS) {
            const int nxt = sp * CPS + cl + 1;
            const char* esrc = (const char*)(g_ebf + (size_t)nxt * CTAN * D);
#pragma unroll 4
            for (int i = tid; i < 4096; i += 256) {
                int r = i >> 5, c = i & 31;
                cpa16(sb + ES_OFF(1 - cur) + r * SROW + c * 16, esrc + r * 512 + c * 16);
            }
            if (tid < 32) cpa16(sb + ESQ_OFF(1 - cur) + tid * 16,
                                (const char*)(g_esq + nxt * CTAN) + tid * 16);
            CP_COMMIT();
        }

        float acc[16][4];
#pragma unroll
        for (int nb = 0; nb < 16; ++nb)
#pragma unroll
            for (int q = 0; q < 4; ++q) acc[nb][q] = 0.f;

        const uint32_t bBase = sb + ES_OFF(cur) + bRowOff;
#pragma unroll
        for (int ks = 0; ks < 16; ++ks) {
            uint32_t a0, a1, a2, a3;
            ldsm4(a0, a1, a2, a3, aBase + ks * 32);
#pragma unroll
            for (int nbp = 0; nbp < 8; ++nbp) {
                uint32_t b0, b1, b2, b3;
                ldsm4(b0, b1, b2, b3, bBase + nbp * (16 * SROW) + ks * 32);
                mma_bf16(acc[2 * nbp][0], acc[2 * nbp][1], acc[2 * nbp][2], acc[2 * nbp][3],
                         a0, a1, a2, a3, b0, b1);
                mma_bf16(acc[2 * nbp + 1][0], acc[2 * nbp + 1][1], acc[2 * nbp + 1][2], acc[2 * nbp + 1][3],
                         a0, a1, a2, a3, b2, b3);
            }
        }

        // ---- epilogue: approx scores, chunk-min, running-min, collect ----
        const int chunk = sp * CPS + cl;
        const int code0 = chunk * CTAN;
        const float* esqs = reinterpret_cast<const float*>(smc + ESQ_OFF(cur));
        float m0 = 3.4e38f, m1 = 3.4e38f;
#pragma unroll
        for (int nb = 0; nb < 16; ++nb) {
            float2 ee = *reinterpret_cast<const float2*>(esqs + nb * 8 + 2 * t4);
            float s00 = fmaf(-2.f, acc[nb][0], zq0 + ee.x);
            float s01 = fmaf(-2.f, acc[nb][1], zq0 + ee.y);
            float s10 = fmaf(-2.f, acc[nb][2], zq1 + ee.x);
            float s11 = fmaf(-2.f, acc[nb][3], zq1 + ee.y);
            acc[nb][0] = s00; acc[nb][1] = s01; acc[nb][2] = s10; acc[nb][3] = s11;
            m0 = fminf(m0, fminf(s00, s01));
            m1 = fminf(m1, fminf(s10, s11));
        }
        // quad-reduce (lanes sharing g)
        m0 = fminf(m0, __shfl_xor_sync(0xffffffffu, m0, 1));
        m0 = fminf(m0, __shfl_xor_sync(0xffffffffu, m0, 2));
        m1 = fminf(m1, __shfl_xor_sync(0xffffffffu, m1, 1));
        m1 = fminf(m1, __shfl_xor_sync(0xffffffffu, m1, 2));
        run0 = fminf(run0, m0);
        run1 = fminf(run1, m1);
        const float thr0 = run0 + WINDOW, thr1 = run1 + WINDOW;

#pragma unroll
        for (int nb = 0; nb < 16; ++nb) {
            const int cb = code0 + nb * 8 + 2 * t4;
            if (acc[nb][0] <= thr0) {
                int p = atomicAdd(&g_ccount[tokg], 1);
                if (p < CAP) g_cand[(size_t)tokg * CAP + p] = cb;
            }
            if (acc[nb][1] <= thr0) {
                int p = atomicAdd(&g_ccount[tokg], 1);
                if (p < CAP) g_cand[(size_t)tokg * CAP + p] = cb + 1;
            }
            if (acc[nb][2] <= thr1) {
                int p = atomicAdd(&g_ccount[tokg + 8], 1);
                if (p < CAP) g_cand[(size_t)(tokg + 8) * CAP + p] = cb;
            }
            if (acc[nb][3] <= thr1) {
                int p = atomicAdd(&g_ccount[tokg + 8], 1);
                if (p < CAP) g_cand[(size_t)(tokg + 8) * CAP + p] = cb + 1;
            }
        }
        __syncthreads();   // all warps done with buf[cur] before it is refilled
    }
}

// ============================================================
// Kernel 2: exact rescore of candidates — bit-exact quantized score,
//   lexicographic (value, index) min = reference argmin.
// ============================================================
__global__ void rescore_kernel(const float* __restrict__ z, const float* __restrict__ emb) {
    const int w = (blockIdx.x << 3) + (threadIdx.x >> 5);
    const int lane = threadIdx.x & 31;
    const int cnt = g_ccount[w];
    const float4* zr = reinterpret_cast<const float4*>(z + (size_t)w * D);
    const float zq = g_zsq[w];
    float bs = 3.4e38f; int bi = 0x7fffffff;

    if (cnt > 0 && cnt <= CAP) {
        for (int j = lane; j < cnt; j += 32) {
            int code = g_cand[(size_t)w * CAP + j];
            const float4* er = reinterpret_cast<const float4*>(emb + (size_t)code * D);
            float acc = 0.f;
#pragma unroll
            for (int i = 0; i < D / 4; ++i) {
                float4 a = zr[i], b = er[i];
                acc = fmaf(a.x, b.x, acc); acc = fmaf(a.y, b.y, acc);
                acc = fmaf(a.z, b.z, acc); acc = fmaf(a.w, b.w, acc);
            }
            float t1 = __fadd_rn(zq, g_esq[code]);
            float s  = __fadd_rn(t1, -2.0f * acc);
            if (s < bs || (s == bs && code < bi)) { bs = s; bi = code; }
        }
    } else {
        // overflow (or empty) fallback: exact full scan, 4-way ILP
        for (int c0 = lane; c0 < KCODES; c0 += 128) {
            const float4* e0 = reinterpret_cast<const float4*>(emb + (size_t)c0 * D);
            const float4* e1 = reinterpret_cast<const float4*>(emb + (size_t)(c0 + 32) * D);
            const float4* e2 = reinterpret_cast<const float4*>(emb + (size_t)(c0 + 64) * D);
            const float4* e3 = reinterpret_cast<const float4*>(emb + (size_t)(c0 + 96) * D);
            float a0 = 0.f, a1 = 0.f, a2 = 0.f, a3 = 0.f;
#pragma unroll 4
            for (int i = 0; i < D / 4; ++i) {
                float4 zv = zr[i];
                float4 v0 = e0[i], v1 = e1[i], v2 = e2[i], v3 = e3[i];
                a0 = fmaf(zv.x, v0.x, a0); a0 = fmaf(zv.y, v0.y, a0);
                a0 = fmaf(zv.z, v0.z, a0); a0 = fmaf(zv.w, v0.w, a0);
                a1 = fmaf(zv.x, v1.x, a1); a1 = fmaf(zv.y, v1.y, a1);
                a1 = fmaf(zv.z, v1.z, a1); a1 = fmaf(zv.w, v1.w, a1);
                a2 = fmaf(zv.x, v2.x, a2); a2 = fmaf(zv.y, v2.y, a2);
                a2 = fmaf(zv.z, v2.z, a2); a2 = fmaf(zv.w, v2.w, a2);
                a3 = fmaf(zv.x, v3.x, a3); a3 = fmaf(zv.y, v3.y, a3);
                a3 = fmaf(zv.z, v3.z, a3); a3 = fmaf(zv.w, v3.w, a3);
            }
            float s0 = __fadd_rn(__fadd_rn(zq, g_esq[c0]),      -2.0f * a0);
            float s1 = __fadd_rn(__fadd_rn(zq, g_esq[c0 + 32]), -2.0f * a1);
            float s2 = __fadd_rn(__fadd_rn(zq, g_esq[c0 + 64]), -2.0f * a2);
            float s3 = __fadd_rn(__fadd_rn(zq, g_esq[c0 + 96]), -2.0f * a3);
            if (s0 < bs || (s0 == bs && c0      < bi)) { bs = s0; bi = c0;      }
            if (s1 < bs || (s1 == bs && c0 + 32 < bi)) { bs = s1; bi = c0 + 32; }
            if (s2 < bs || (s2 == bs && c0 + 64 < bi)) { bs = s2; bi = c0 + 64; }
            if (s3 < bs || (s3 == bs && c0 + 96 < bi)) { bs = s3; bi = c0 + 96; }
        }
    }
#pragma unroll
    for (int m = 16; m >= 1; m >>= 1) {
        float ov = __shfl_xor_sync(0xffffffffu, bs, m);
        int   oi = __shfl_xor_sync(0xffffffffu, bi, m);
        if (ov < bs || (ov == bs && oi < bi)) { bs = ov; bi = oi; }
    }
    if (lane == 0) g_bidx[w] = bi;
}

// ============================================================
// Kernel 3: gather + straight-through output + loss partials
//   exact replication of fl(z + fl(e - z))
// ============================================================
__global__ void gather_kernel(const float* __restrict__ z, const float* __restrict__ emb,
                              float* __restrict__ out, int out_size) {
    __shared__ float wsum[8];
    const int lane = threadIdx.x & 31;
    const int wib  = threadIdx.x >> 5;
    const int n    = blockIdx.x * 8 + wib;

    const int idx = g_bidx[n];
    const float4* zr = reinterpret_cast<const float4*>(z   + (size_t)n   * D);
    const float4* er = reinterpret_cast<const float4*>(emb + (size_t)idx * D);
    float4* orow = reinterpret_cast<float4*>(out + (size_t)n * D);

    float ss = 0.f;
#pragma unroll
    for (int i = lane; i < D / 4; i += 32) {
        float4 zv = zr[i], ev = er[i], df, ov;
        df.x = ev.x - zv.x; df.y = ev.y - zv.y; df.z = ev.z - zv.z; df.w = ev.w - zv.w;
        ov.x = zv.x + df.x; ov.y = zv.y + df.y; ov.z = zv.z + df.z; ov.w = zv.w + df.w;
        ss = fmaf(df.x, df.x, ss); ss = fmaf(df.y, df.y, ss);
        ss = fmaf(df.z, df.z, ss); ss = fmaf(df.w, df.w, ss);
        if ((size_t)out_size >= ZQ_ELEMS) orow[i] = ov;
    }
#pragma unroll
    for (int m = 16; m >= 1; m >>= 1) ss += __shfl_xor_sync(0xffffffffu, ss, m);
    if (lane == 0) wsum[wib] = ss;
    __syncthreads();
    if (threadIdx.x == 0) {
        float t = 0.f;
#pragma unroll
        for (int w = 0; w < 8; ++w) t += wsum[w];
        g_part[blockIdx.x] = t;
    }
    if (lane == 0 && (size_t)out_size >= OUT_FULL)
        out[ZQ_ELEMS + 3 + n] = (float)idx;
}

// ============================================================
// Kernel 4: deterministic loss finalize (double accumulation)
// ============================================================
__global__ void loss_kernel(float* __restrict__ out, int out_size) {
    __shared__ double sh[256];
    const int t = threadIdx.x;
    double s = 0.0;
#pragma unroll 4
    for (int i = t * (GBLOCKS / 256); i < (t + 1) * (GBLOCKS / 256); ++i)
        s += (double)g_part[i];
    sh[t] = s;
    __syncthreads();
    for (int m = 128; m >= 1; m >>= 1) {
        if (t < m) sh[t] += sh[t + m];
        __syncthreads();
    }
    if (t == 0 && (size_t)out_size >= ZQ_ELEMS + 3) {
        float mean = (float)(sh[0] / (double)ZQ_ELEMS);
        float commit   = 0.25f * mean;
        float codebook = mean;
        out[ZQ_ELEMS + 0] = commit + codebook;
        out[ZQ_ELEMS + 1] = commit;
        out[ZQ_ELEMS + 2] = codebook;
    }
}

// ============================================================
extern "C" void kernel_launch(void* const* d_in, const int* in_sizes, int n_in,
                              void* d_out, int out_size) {
    const float* z   = (const float*)d_in[0];
    const float* emb = (const float*)d_in[1];
    if (n_in >= 2 && in_sizes[0] == KCODES * D && in_sizes[1] == NTOK * D) {
        z   = (const float*)d_in[1];
        emb = (const float*)d_in[0];
    }
    float* out = (float*)d_out;

    static bool attr_set = false;
    if (!attr_set) {
        cudaFuncSetAttribute(filter_kernel,
                             cudaFuncAttributeMaxDynamicSharedMemorySize, SMEM_TOTAL);
        attr_set = true;
    }

    esq_kernel  <<<KCODES / 128, 128>>>(emb);
    zsq_kernel  <<<NTOK / 256, 256>>>(z);
    convz_kernel<<<(NTOK * 32) / 256, 256>>>(z);
    conve_kernel<<<(KCODES * 32) / 256, 256>>>(emb);
    init_kernel <<<NTOK / 256, 256>>>();
    filter_kernel<<<NTILES * NSPLIT, 256, SMEM_TOTAL>>>();
    rescore_kernel<<<NTOK / 8, 256>>>(z, emb);
    gather_kernel<<<GBLOCKS, 256>>>(z, emb, out, out_size);
    loss_kernel <<<1, 256>>>(out, out_size);
}